// round 16
// baseline (speedup 1.0000x reference)
#include <cuda_runtime.h>
#include <math.h>

typedef unsigned long long ull;

// ---------------- problem constants ----------------
#define NT       256     // 8 warps; two independent 128-thread groups
#define BT       16      // batch items per block -> 128 blocks
#define T_STEPS  128
#define STATE    115
#define ACT      39
#define CIN      154
#define COUT     116

// duplicated-activation layout: value at logical col c lives at [2c] and [2c+1]
#define SBUF2 264        // 132 logical cols * 2
#define SA2   88         // 44 logical cols * 2

// ---------------- shared memory layout (float offsets) ----------------
#define OW0   0          // padded [156][16]
#define OW1   2496
#define OW2   3008
#define OW3   5056
#define OW4   13248
#define OW5   21440
#define OW6   23488
#define OW7   24000
#define OW8   24128      // padded [8][120]
#define OWR   25088      // 348
#define OB0   25436
#define OB1   25452
#define OB2   25484
#define OB3   25548
#define OB4   25676
#define OB5   25740
#define OB6   25772
#define OB7   25788
#define OB8   25796      // 120 padded
#define OBR   25916
#define OBUFA 25920      // 16*264 = 4224 (dup)
#define OBUFB 30144      // 4224 (dup)
#define OXS   34368      // 4224 (dup; logical cols >=115 zero)
#define OAB0  38592      // 16*88 = 1408 (dup; cols >=39 zero)
#define OAB1  40000      // 1408
#define OSCR  41408      // 1024 floats (L0 partials, packed ull, non-dup)
#define SMEM_FLOATS 42432
#define SMEM_BYTES  (SMEM_FLOATS * 4)   // 169728 B -> 1 CTA/SM

#define GBAR() asm volatile("bar.sync %0, 128;" :: "r"(grp + 1) : "memory")

struct Params {
    const float* u;
    const float* W[9];
    const float* b[9];
    const float* Wr;
    const float* br;
    float* out;
};

// ---- packed f32x2 helpers ----
__device__ __forceinline__ ull pk2(float x, float y) {
    ull r; asm("mov.b64 %0, {%1, %2};" : "=l"(r) : "f"(x), "f"(y)); return r;
}
__device__ __forceinline__ void upk2(ull v, float& x, float& y) {
    asm("mov.b64 {%0, %1}, %2;" : "=f"(x), "=f"(y) : "l"(v));
}
__device__ __forceinline__ ull fma2(ull a, ull b, ull c) {
    ull d; asm("fma.rn.f32x2 %0, %1, %2, %3;" : "=l"(d) : "l"(a), "l"(b), "l"(c)); return d;
}

__device__ __forceinline__ void cpy_sh(float* dst, const float* __restrict__ src, int n) {
    for (int k = threadIdx.x; k < n; k += NT) dst[k] = src[k];
}

// ---- TB=2 layer on dup-act buffers. og = gtid>>2 (32 slots), bp = gtid&3;
// thread handles items (bp, bp+4). Acts loaded as ulonglong2 = two (a,a) pairs.
template<int FI, int FO, int TO, int WS, bool CLIP, bool RESID>
__device__ __forceinline__ void layerN(const float* __restrict__ W,
                                       const float* __restrict__ bias,
                                       const float* __restrict__ in,
                                       float* __restrict__ out,
                                       int og, int bp) {
    constexpr int OG = FO / TO;
    static_assert(FI % 2 == 0, "even FI required");
    if (og < OG) {
        const int o0 = og * TO;
        const float* i0 = in + bp * SBUF2;
        const float* i1 = in + (bp + 4) * SBUF2;
        ull aA0, aB0, aA1, aB1;
        if constexpr (TO == 2) {
            float2 bv = *(const float2*)(bias + o0);
            aA0 = pk2(bv.x, bv.y); aA1 = aA0;
        } else {
            float4 bv = *(const float4*)(bias + o0);
            aA0 = pk2(bv.x, bv.y); aB0 = pk2(bv.z, bv.w);
            aA1 = aA0;             aB1 = aB0;
        }
#pragma unroll
        for (int i2 = 0; i2 < FI / 2; ++i2) {
            ulonglong2 v0 = *(const ulonglong2*)(i0 + 4 * i2);  // rows 2i2, 2i2+1 (item0)
            ulonglong2 v1 = *(const ulonglong2*)(i1 + 4 * i2);  // (item1)
            const int r = 2 * i2;
            if constexpr (TO == 2) {
                ull w0 = *(const ull*)(W + r * WS + o0);
                ull w1 = *(const ull*)(W + (r + 1) * WS + o0);
                aA0 = fma2(v0.x, w0, aA0);
                aA1 = fma2(v1.x, w0, aA1);
                aA0 = fma2(v0.y, w1, aA0);
                aA1 = fma2(v1.y, w1, aA1);
            } else {
                ulonglong2 w0 = *(const ulonglong2*)(W + r * WS + o0);
                ulonglong2 w1 = *(const ulonglong2*)(W + (r + 1) * WS + o0);
                aA0 = fma2(v0.x, w0.x, aA0); aB0 = fma2(v0.x, w0.y, aB0);
                aA1 = fma2(v1.x, w0.x, aA1); aB1 = fma2(v1.x, w0.y, aB1);
                aA0 = fma2(v0.y, w1.x, aA0); aB0 = fma2(v0.y, w1.y, aB0);
                aA1 = fma2(v1.y, w1.x, aA1); aB1 = fma2(v1.y, w1.y, aB1);
            }
        }
#pragma unroll
        for (int it = 0; it < 2; ++it) {
            float* op = out + (bp + 4 * it) * SBUF2 + 2 * o0;
            ull pa = it ? aA1 : aA0;
            if constexpr (TO == 2) {
                float r0, r1; upk2(pa, r0, r1);
                if constexpr (CLIP) {
                    r0 = fminf(fmaxf(r0, 0.0f), 6.0f);
                    r1 = fminf(fmaxf(r1, 0.0f), 6.0f);
                }
                *(float4*)op = make_float4(r0, r0, r1, r1);
            } else {
                ull pb = it ? aB1 : aB0;
                float r0, r1, r2, r3;
                upk2(pa, r0, r1); upk2(pb, r2, r3);
                if constexpr (CLIP) {
                    r0 = fminf(fmaxf(r0, 0.0f), 6.0f);
                    r1 = fminf(fmaxf(r1, 0.0f), 6.0f);
                    r2 = fminf(fmaxf(r2, 0.0f), 6.0f);
                    r3 = fminf(fmaxf(r3, 0.0f), 6.0f);
                }
                if constexpr (RESID) {
                    float4 x01 = *(const float4*)op;
                    float4 x23 = *(const float4*)(op + 4);
                    x01.x += r0; x01.y += r0; x01.z += r1; x01.w += r1;
                    x23.x += r2; x23.y += r2; x23.z += r3; x23.w += r3;
                    *(float4*)op = x01;
                    *(float4*)(op + 4) = x23;
                } else {
                    *(float4*)op = make_float4(r0, r0, r1, r1);
                    *(float4*)(op + 4) = make_float4(r2, r2, r3, r3);
                }
            }
        }
    }
}

// ---- L0 partial on dup buffers: NF2 row-pairs for two items ----
template<int NF2>
__device__ __forceinline__ void l0_part2(const float* __restrict__ s0,
                                         const float* __restrict__ s1,
                                         const float* __restrict__ W,
                                         ull& a0, ull& a1) {
#pragma unroll
    for (int i2 = 0; i2 < NF2; ++i2) {
        ulonglong2 v0 = *(const ulonglong2*)(s0 + 4 * i2);
        ulonglong2 v1 = *(const ulonglong2*)(s1 + 4 * i2);
        ull w0 = *(const ull*)(W + (2 * i2) * 16);
        ull w1 = *(const ull*)(W + (2 * i2 + 1) * 16);
        a0 = fma2(v0.x, w0, a0);
        a1 = fma2(v1.x, w0, a1);
        a0 = fma2(v0.y, w1, a0);
        a1 = fma2(v1.y, w1, a1);
    }
}

// reward on dup XS: 16 lanes per item
__device__ __forceinline__ void reward16(const float* __restrict__ sh,
                                         float* __restrict__ out,
                                         int b0, int itemBase, int gtid, int t) {
    const int it = itemBase + (gtid >> 4);
    const int l = gtid & 15;
    float p0 = 0.f, p1 = 0.f, p2 = 0.f;
    const float* xr = sh + OXS + it * SBUF2;
    const float* Wr = sh + OWR;
#pragma unroll
    for (int i = l; i < STATE; i += 16) {
        float v = xr[2 * i];
        p0 = fmaf(v, Wr[3 * i + 0], p0);
        p1 = fmaf(v, Wr[3 * i + 1], p1);
        p2 = fmaf(v, Wr[3 * i + 2], p2);
    }
#pragma unroll
    for (int off = 8; off > 0; off >>= 1) {
        p0 += __shfl_down_sync(0xffffffffu, p0, off, 16);
        p1 += __shfl_down_sync(0xffffffffu, p1, off, 16);
        p2 += __shfl_down_sync(0xffffffffu, p2, off, 16);
    }
    if (l == 0) {
        p0 += sh[OBR + 0]; p1 += sh[OBR + 1]; p2 += sh[OBR + 2];
        out[((size_t)(b0 + it) * T_STEPS + t) * COUT + STATE] =
            -sqrtf(p0 * p0 + p1 * p1 + p2 * p2);
    }
}

__global__ void __launch_bounds__(NT, 1) worldnet_kernel(Params p) {
    extern __shared__ float sh[];
    const int tid = threadIdx.x;
    const int grp = tid >> 7;       // 0 or 1
    const int gtid = tid & 127;
    const int og = gtid >> 2;       // 0..31
    const int bp = gtid & 3;        // 0..3
    const int b0 = blockIdx.x * BT;
    const int itemBase = grp * 8;

    // ---- one-time weight/bias staging ----
    for (int k = tid; k < 156 * 16; k += NT) {
        int r = k >> 4, c = k & 15;
        float v = 0.0f;
        if (r < 115)                  v = p.W[0][r * 16 + c];
        else if (r >= 116 && r < 155) v = p.W[0][(r - 1) * 16 + c];
        sh[OW0 + k] = v;
    }
    cpy_sh(sh + OW1, p.W[1], 16 * 32);
    cpy_sh(sh + OW2, p.W[2], 32 * 64);
    cpy_sh(sh + OW3, p.W[3], 64 * 128);
    cpy_sh(sh + OW4, p.W[4], 128 * 64);
    cpy_sh(sh + OW5, p.W[5], 64 * 32);
    cpy_sh(sh + OW6, p.W[6], 32 * 16);
    cpy_sh(sh + OW7, p.W[7], 16 * 8);
    for (int k = tid; k < 8 * 120; k += NT) {
        int i = k / 120, o = k - i * 120;
        sh[OW8 + k] = (o < STATE) ? p.W[8][i * STATE + o] : 0.0f;
    }
    for (int k = tid; k < 348; k += NT)
        sh[OWR + k] = (k < STATE * 3) ? p.Wr[k] : 0.0f;
    cpy_sh(sh + OB0, p.b[0], 16);
    cpy_sh(sh + OB1, p.b[1], 32);
    cpy_sh(sh + OB2, p.b[2], 64);
    cpy_sh(sh + OB3, p.b[3], 128);
    cpy_sh(sh + OB4, p.b[4], 64);
    cpy_sh(sh + OB5, p.b[5], 32);
    cpy_sh(sh + OB6, p.b[6], 16);
    cpy_sh(sh + OB7, p.b[7], 8);
    for (int k = tid; k < 120; k += NT)
        sh[OB8 + k] = (k < STATE) ? p.b[8][k] : 0.0f;
    for (int k = tid; k < 4; k += NT)
        sh[OBR + k] = (k < 3) ? p.br[k] : 0.0f;

    // ---- init XS dup (logical cols >= 115 zero) ----
    for (int k = tid; k < BT * SBUF2; k += NT) {
        int b = k / SBUF2, c = k - b * SBUF2;
        int i = c >> 1;
        sh[OXS + k] = (i < STATE)
            ? p.u[(size_t)(b0 + b) * T_STEPS * CIN + i] : 0.0f;
    }
    // actions for t=0 into OAB0 (dup); zero pad cols of both buffers
    for (int k = tid; k < BT * ACT; k += NT) {
        int b = k / ACT, j = k - b * ACT;
        float v = p.u[(size_t)(b0 + b) * T_STEPS * CIN + STATE + j];
        *(float2*)(sh + OAB0 + b * SA2 + 2 * j) = make_float2(v, v);
    }
    if (tid < 2 * BT) {
        int buf = tid >> 4, b = tid & 15;
        float* ab = sh + (buf ? OAB1 : OAB0) + b * SA2;
#pragma unroll
        for (int j = ACT; j < 44; ++j)
            *(float2*)(ab + 2 * j) = make_float2(0.0f, 0.0f);
    }
    __syncthreads();
    // after this point the two groups never share a barrier

    const float* bufAG = sh + OBUFA + itemBase * SBUF2;
    float* bufAGw = sh + OBUFA + itemBase * SBUF2;
    const float* bufBG = sh + OBUFB + itemBase * SBUF2;
    float* bufBGw = sh + OBUFB + itemBase * SBUF2;
    float* xsGw   = sh + OXS   + itemBase * SBUF2;

    // ---- time loop (group-independent) ----
    for (int t = 0; t < T_STEPS; ++t) {
        if (t > 0) reward16(sh, p.out, b0, itemBase, gtid, t - 1);
        // out[:, t, 0:116] = x_t (compact from dup layout)
        {
            const int it = itemBase + (gtid >> 4);
            for (int c = gtid & 15; c < 29; c += 16) {
                const float* xp = sh + OXS + it * SBUF2 + 8 * c;
                float4 a = *(const float4*)xp;        // (x0,x0,x1,x1)
                float4 b = *(const float4*)(xp + 4);  // (x2,x2,x3,x3)
                *(float4*)(p.out + ((size_t)(b0 + it) * T_STEPS + t) * COUT + 4 * c) =
                    make_float4(a.x, a.z, b.x, b.z);
            }
        }
        // prefetch actions for t+1 into the other buffer (dup)
        if (t < T_STEPS - 1) {
            const int it = itemBase + (gtid >> 4);
            float* ab = sh + (((t + 1) & 1) ? OAB1 : OAB0) + it * SA2;
            const float* us = p.u + ((size_t)(b0 + it) * T_STEPS + t + 1) * CIN + STATE;
            for (int j = gtid & 15; j < ACT; j += 16) {
                float v = us[j];
                *(float2*)(ab + 2 * j) = make_float2(v, v);
            }
        }
        // ---- L0 partial: 8 output-pairs x 4 K-quarters ----
        {
            const int pg = og & 7;
            const int q  = og >> 3;
            const int o0 = pg * 2;
            ull a0, a1;
            if (q == 0) {
                float2 bv = *(const float2*)(sh + OB0 + o0);
                a0 = pk2(bv.x, bv.y); a1 = a0;
            } else { a0 = 0ull; a1 = 0ull; }
            const int i0 = itemBase + bp, i1 = i0 + 4;
            const float* x0 = sh + OXS + i0 * SBUF2;
            const float* x1 = sh + OXS + i1 * SBUF2;
            const float* abase = sh + ((t & 1) ? OAB1 : OAB0);
            if (q == 0)      l0_part2<20>(x0,       x1,       sh + OW0 + o0,            a0, a1);
            else if (q == 1) l0_part2<20>(x0 + 80,  x1 + 80,  sh + OW0 + 40 * 16 + o0,  a0, a1);
            else if (q == 2) l0_part2<18>(x0 + 160, x1 + 160, sh + OW0 + 80 * 16 + o0,  a0, a1);
            else             l0_part2<20>(abase + i0 * SA2, abase + i1 * SA2,
                                          sh + OW0 + 116 * 16 + o0, a0, a1);
            *(ull*)(sh + OSCR + (i0 * 8 + pg) * 8 + q * 2) = a0;
            *(ull*)(sh + OSCR + (i1 * 8 + pg) * 8 + q * 2) = a1;
        }
        GBAR();
        if (gtid < 64) {   // combine quarters -> OBUFB (dup)
            const int pg = gtid & 7;
            const int it = itemBase + (gtid >> 3);
            const float* base = sh + OSCR + (it * 8 + pg) * 8;
            ulonglong2 v01 = *(const ulonglong2*)(base);
            ulonglong2 v23 = *(const ulonglong2*)(base + 4);
            float a0, a1, c0, c1, d0, d1, e0, e1;
            upk2(v01.x, a0, a1); upk2(v01.y, c0, c1);
            upk2(v23.x, d0, d1); upk2(v23.y, e0, e1);
            float lo = (a0 + c0) + (d0 + e0);
            float hi = (a1 + c1) + (d1 + e1);
            lo = fminf(fmaxf(lo, 0.0f), 6.0f);
            hi = fminf(fmaxf(hi, 0.0f), 6.0f);
            *(float4*)(sh + OBUFB + it * SBUF2 + 4 * pg) =
                make_float4(lo, lo, hi, hi);
        }
        GBAR();

        //            FI   FO  TO  WS    CLIP  RESID
        layerN< 16,  32, 2,  32, true, false>(sh + OW1, sh + OB1, bufBG, bufAGw, og, bp); GBAR();
        layerN< 32,  64, 4,  64, true, false>(sh + OW2, sh + OB2, bufAG, bufBGw, og, bp); GBAR();
        layerN< 64, 128, 4, 128, true, false>(sh + OW3, sh + OB3, bufBG, bufAGw, og, bp); GBAR();
        layerN<128,  64, 4,  64, true, false>(sh + OW4, sh + OB4, bufAG, bufBGw, og, bp); GBAR();
        layerN< 64,  32, 2,  32, true, false>(sh + OW5, sh + OB5, bufBG, bufAGw, og, bp); GBAR();
        layerN< 32,  16, 2,  16, true, false>(sh + OW6, sh + OB6, bufAG, bufBGw, og, bp); GBAR();
        layerN< 16,   8, 2,   8, true, false>(sh + OW7, sh + OB7, bufBG, bufAGw, og, bp); GBAR();
        // L8 (8 -> 120 padded, 116 real) fused residual into XS (dup)
        layerN<  8, 120, 4, 120, false, true>(sh + OW8, sh + OB8, bufAG, xsGw, og, bp); GBAR();
        // loop back: top segment needs no extra barrier
    }
    // trailing reward for t = 127
    reward16(sh, p.out, b0, itemBase, gtid, T_STEPS - 1);
}

extern "C" void kernel_launch(void* const* d_in, const int* in_sizes, int n_in,
                              void* d_out, int out_size) {
    Params p;
    p.u = (const float*)d_in[0];
    for (int i = 0; i < 9; ++i) {
        p.W[i] = (const float*)d_in[1 + 2 * i];
        p.b[i] = (const float*)d_in[2 + 2 * i];
    }
    p.Wr = (const float*)d_in[19];
    p.br = (const float*)d_in[20];
    p.out = (float*)d_out;

    cudaFuncSetAttribute(worldnet_kernel,
                         cudaFuncAttributeMaxDynamicSharedMemorySize, SMEM_BYTES);
    worldnet_kernel<<<2048 / BT, NT, SMEM_BYTES>>>(p);
}